// round 15
// baseline (speedup 1.0000x reference)
#include <cuda_runtime.h>
#include <cstdint>

typedef unsigned long long ull;

#define BB 4
#define LL 4096
#define HH 8
#define DD 64
#define SK 45
#define NT 45
#define BH (BB*HH)      /* 32 */
#define SEG 16
#define KSEG (LL/SEG)   /* 256 keys per segment */
#define CH 32           /* cumsum chunk length */
#define NCH (LL/CH)     /* 128 chunks */

// ---------------- scratch (__device__ globals: no allocation allowed) -------
__device__ float g_M[BB*HH*LL];              // 512 KB
__device__ int   g_Mtop[BB*HH*NT];
__device__ float g_logits[(size_t)BB*HH*NT*LL]; // 23.6 MB (logits, then probs)
__device__ float g_oatt[BB*HH*NT*DD];        // attention rows (atomic accum)
__device__ float g_csum[BB*HH*NCH*DD];       // chunk sums / exclusive prefixes

// ---------------- packed f32x2 helpers --------------------------------------
__device__ __forceinline__ void fma2(ull& d, ull a, ull b) {
    asm("fma.rn.f32x2 %0, %1, %2, %0;" : "+l"(d) : "l"(a), "l"(b));
}
__device__ __forceinline__ void add2(ull& a, ull b) {
    asm("add.rn.f32x2 %0, %0, %1;" : "+l"(a) : "l"(b));
}
__device__ __forceinline__ ull pack2(float a, float b) {
    ull r; asm("mov.b64 %0, {%1, %2};" : "=l"(r) : "f"(a), "f"(b)); return r;
}
__device__ __forceinline__ float f2lo(ull x) { return __uint_as_float((unsigned)x); }
__device__ __forceinline__ float f2hi(ull x) { return __uint_as_float((unsigned)(x >> 32)); }

// ============================================================================
// Kernel 1 (v5): M[b,h,l] = max_j(q·k_sample_j) - sum_j(q·k_sample_j)/L
// 8-lane groups: group owns one (query, head); lane e covers 16B chunks
// e, e+8 of the 256B row, so each warp LDG.128 covers 4 FULLY-USED 128B
// lines (nL=4 vs 8 before -> half the L1tex wavefront cost).
// Block = 4 queries x 8 heads (one b). idx staged in smem.
// ============================================================================
__global__ __launch_bounds__(256) void k_m(const float* __restrict__ q,
                                           const float* __restrict__ k,
                                           const int* __restrict__ idx) {
    __shared__ int sidx[4 * 48];
    int tid = threadIdx.x;
    int qy0 = blockIdx.x * 4;                    // 4 queries per block
    int b  = qy0 >> 12;
    int l0 = qy0 & (LL - 1);

    for (int i = tid; i < 4 * SK; i += 256) {
        int ql = i / SK, j = i - ql * SK;
        sidx[ql * 48 + j] = idx[(size_t)(l0 + ql) * SK + j];
    }
    __syncthreads();

    int wid = tid >> 5, lane = tid & 31;
    int ql = wid >> 1;                           // 0..3
    int h  = ((wid & 1) << 2) + (lane >> 3);     // head 0..7
    int e  = lane & 7;                           // octant of the 256B row
    int l  = l0 + ql;

    const float* qrow = q + ((size_t)(b * LL + l) * HH + h) * DD;
    ull qd[4];
#pragma unroll
    for (int i = 0; i < 2; i++) {
        ulonglong2 v = *(const ulonglong2*)(qrow + i * 32 + e * 4);
        qd[2*i] = v.x; qd[2*i+1] = v.y;
    }

    const float* kbase = k + (size_t)b * LL * HH * DD + h * DD;
    const int* srow = &sidx[ql * 48];

    float mx = -INFINITY, sm = 0.f;
#pragma unroll 3
    for (int j = 0; j < SK; j++) {
        int ki = srow[j];
        const float* krow = kbase + (size_t)ki * (HH * DD);
        ull a0 = 0, a1 = 0;
#pragma unroll
        for (int i = 0; i < 2; i++) {
            ulonglong2 v = *(const ulonglong2*)(krow + i * 32 + e * 4);
            fma2(a0, qd[2*i],   v.x);
            fma2(a1, qd[2*i+1], v.y);
        }
        add2(a0, a1);
        float sh = f2lo(a0) + f2hi(a0);
        sh += __shfl_xor_sync(0xffffffffu, sh, 1);
        sh += __shfl_xor_sync(0xffffffffu, sh, 2);
        sh += __shfl_xor_sync(0xffffffffu, sh, 4);
        mx = fmaxf(mx, sh);
        sm += sh;
    }
    if (e == 0) g_M[(size_t)(b * HH + h) * LL + l] = mx - sm * (1.0f / LL);
}

// ============================================================================
// Kernel 2: stable top-45 per (b,h) via iterative argmax (ties -> min index,
// matching jax.lax.top_k). Winners sorted ascending.
// ============================================================================
__global__ __launch_bounds__(256) void k_topk() {
    int bh  = blockIdx.x;
    int tid = threadIdx.x;   // 256
    __shared__ float wv[8];
    __shared__ int   wi[8];
    __shared__ int   winner;
    __shared__ int   winners[NT];

    float rv[16];
#pragma unroll
    for (int s = 0; s < 16; s++) rv[s] = g_M[(size_t)bh * LL + tid + s * 256];

    for (int it = 0; it < NT; it++) {
        float bv = -INFINITY; int bi = 1 << 30;
#pragma unroll
        for (int s = 0; s < 16; s++) {
            int i = tid + s * 256;
            float v = rv[s];
            if (v > bv || (v == bv && i < bi)) { bv = v; bi = i; }
        }
        for (int o = 16; o; o >>= 1) {
            float ov = __shfl_down_sync(0xffffffffu, bv, o);
            int   oi = __shfl_down_sync(0xffffffffu, bi, o);
            if (ov > bv || (ov == bv && oi < bi)) { bv = ov; bi = oi; }
        }
        if ((tid & 31) == 0) { wv[tid >> 5] = bv; wi[tid >> 5] = bi; }
        __syncthreads();
        if (tid == 0) {
            float fv = wv[0]; int fi = wi[0];
            for (int w = 1; w < 8; w++)
                if (wv[w] > fv || (wv[w] == fv && wi[w] < fi)) { fv = wv[w]; fi = wi[w]; }
            winner = fi;
            winners[it] = fi;
        }
        __syncthreads();
        int wn = winner;
#pragma unroll
        for (int s = 0; s < 16; s++)
            if (tid + s * 256 == wn) rv[s] = -INFINITY;
        __syncthreads();
    }
    if (tid == 0) {
        int w[NT];
        for (int i = 0; i < NT; i++) w[i] = winners[i];
        for (int i = 1; i < NT; i++) {
            int x = w[i], j = i - 1;
            while (j >= 0 && w[j] > x) { w[j + 1] = w[j]; j--; }
            w[j + 1] = x;
        }
        for (int i = 0; i < NT; i++) g_Mtop[bh * NT + i] = w[i];
    }
}

// ============================================================================
// Kernel 3a (v3): logits — barrier-free, warp-autonomous, direct L2.
// grid = BH x SEG, block 192 = 6 warps x 8 u-groups x 4 lanes.
// All groups in a warp read the SAME K row per step (coalescer dedups to
// 256B/warp/key from L2). Each warp loops only to the max pos among its 8
// consecutive-sorted u's — no __syncthreads, no cross-warp imbalance.
// ============================================================================
__global__ __launch_bounds__(192) void k_logits(const float* __restrict__ q,
                                                const float* __restrict__ kk) {
    int bh  = blockIdx.x >> 4;
    int seg = blockIdx.x & 15;
    int b = bh >> 3, h = bh & 7;
    int tid = threadIdx.x;
    int u = tid >> 2, j = tid & 3;
    bool act = (u < NT);
    int pos = act ? g_Mtop[bh * NT + u] : -1;

    int wmax = pos;
#pragma unroll
    for (int o = 16; o; o >>= 1)
        wmax = max(wmax, __shfl_xor_sync(0xffffffffu, wmax, o));

    const float* qrow =
        q + ((size_t)(b * LL + (pos < 0 ? 0 : pos)) * HH + h) * DD;
    ull qd[8];
#pragma unroll
    for (int i = 0; i < 4; i++) {
        ulonglong2 v = *(const ulonglong2*)(qrow + (j + 4 * i) * 4);
        qd[2*i] = v.x; qd[2*i+1] = v.y;
    }

    int k0 = seg * KSEG;
    int kend = min(k0 + KSEG - 1, wmax);
    const float* kb = kk + (size_t)b * LL * HH * DD + h * DD;
    float* lrow = g_logits + (size_t)(bh * NT + (act ? u : NT - 1)) * LL;

#pragma unroll 2
    for (int kg = k0; kg <= kend; kg++) {
        const float* krow = kb + (size_t)kg * (HH * DD);
        ull a0 = 0, a1 = 0;
#pragma unroll
        for (int i = 0; i < 4; i++) {
            ulonglong2 v = *(const ulonglong2*)(krow + (j + 4 * i) * 4);
            fma2(a0, qd[2*i],   v.x);
            fma2(a1, qd[2*i+1], v.y);
        }
        add2(a0, a1);
        float sh = f2lo(a0) + f2hi(a0);
        sh += __shfl_xor_sync(0xffffffffu, sh, 1);
        sh += __shfl_xor_sync(0xffffffffu, sh, 2);
        if (j == 0 && kg <= pos) lrow[kg] = sh * 0.125f;
    }
}

// ============================================================================
// Kernel 3b: in-place softmax over k in [0, pos] for each of the 1440 rows
// ============================================================================
__global__ __launch_bounds__(128) void k_softmax() {
    int row = blockIdx.x;              // bh*NT + u
    int pos = g_Mtop[row];
    int n = pos + 1;
    float* lg = g_logits + (size_t)row * LL;
    int tid = threadIdx.x;             // 128 = 4 warps
    __shared__ float red[4];

    float mx = -INFINITY;
    for (int i = tid; i < n; i += 128) mx = fmaxf(mx, lg[i]);
    for (int o = 16; o; o >>= 1) mx = fmaxf(mx, __shfl_xor_sync(0xffffffffu, mx, o));
    if ((tid & 31) == 0) red[tid >> 5] = mx;
    __syncthreads();
    mx = fmaxf(fmaxf(red[0], red[1]), fmaxf(red[2], red[3]));

    float sm = 0.f;
    for (int i = tid; i < n; i += 128) sm += expf(lg[i] - mx);
    for (int o = 16; o; o >>= 1) sm += __shfl_xor_sync(0xffffffffu, sm, o);
    __syncthreads();
    if ((tid & 31) == 0) red[tid >> 5] = sm;
    __syncthreads();
    sm = red[0] + red[1] + red[2] + red[3];

    float inv = 1.0f / sm;
    for (int i = tid; i < n; i += 128) lg[i] = expf(lg[i] - mx) * inv;
}

// ============================================================================
// zero the attention-output accumulator
// ============================================================================
__global__ void k_zero() {
    int i = blockIdx.x * 256 + threadIdx.x;
    if (i < BH * NT * DD) g_oatt[i] = 0.f;
}

// ============================================================================
// Kernel 3c (v2): PV — barrier-free, warp-autonomous, direct L2.
// Same structure as k_logits v3. Lane j accumulates interleaved d-chunks
// j, j+4, j+8, j+12 (V loads coalesce + dedup to 256B/warp/key).
// Probs masked to 0 beyond pos (0 * finite = 0). Atomic accumulate at end.
// ============================================================================
__global__ __launch_bounds__(192) void k_pv(const float* __restrict__ v) {
    int bh  = blockIdx.x >> 4;
    int seg = blockIdx.x & 15;
    int b = bh >> 3, h = bh & 7;
    int tid = threadIdx.x;
    int u = tid >> 2, j = tid & 3;
    bool act = (u < NT);
    int pos = act ? g_Mtop[bh * NT + u] : -1;

    int wmax = pos;
#pragma unroll
    for (int o = 16; o; o >>= 1)
        wmax = max(wmax, __shfl_xor_sync(0xffffffffu, wmax, o));

    const float* lrow = g_logits + (size_t)(bh * NT + (act ? u : NT - 1)) * LL;
    const float* vb = v + (size_t)b * LL * HH * DD + h * DD;

    ull acc[8];
#pragma unroll
    for (int i = 0; i < 8; i++) acc[i] = 0;

    int k0 = seg * KSEG;
    int kend = min(k0 + KSEG - 1, wmax);

#pragma unroll 2
    for (int kg = k0; kg <= kend; kg++) {
        float p = (kg <= pos) ? lrow[kg] : 0.f;
        ull pp = pack2(p, p);
        const float* vrow = vb + (size_t)kg * (HH * DD);
#pragma unroll
        for (int i = 0; i < 4; i++) {
            ulonglong2 vv = *(const ulonglong2*)(vrow + (j + 4 * i) * 4);
            fma2(acc[2*i],   pp, vv.x);
            fma2(acc[2*i+1], pp, vv.y);
        }
    }

    if (act) {
        float* dst = g_oatt + (size_t)(bh * NT + u) * DD;
#pragma unroll
        for (int i = 0; i < 4; i++) {
            int c = (j + 4 * i) * 4;
            atomicAdd(dst + c + 0, f2lo(acc[2*i]));
            atomicAdd(dst + c + 1, f2hi(acc[2*i]));
            atomicAdd(dst + c + 2, f2lo(acc[2*i+1]));
            atomicAdd(dst + c + 3, f2hi(acc[2*i+1]));
        }
    }
}

// ============================================================================
// cumsum(V) over L, chunked 3-phase scan (CH=32),
// with [B,L,H,D] -> [B,H,L,D] transpose on output
// ============================================================================
__global__ __launch_bounds__(64) void k_csum_a(const float* __restrict__ v) {
    int blk = blockIdx.x;                 // bh*NCH + ch
    int bh = blk >> 7, ch = blk & (NCH - 1);
    int b = bh >> 3, h = bh & 7;
    int d = threadIdx.x;
    float s = 0.f;
    const float* base = v + ((size_t)(b * LL + ch * CH) * HH + h) * DD + d;
#pragma unroll 4
    for (int i = 0; i < CH; i++) s += base[(size_t)i * HH * DD];
    g_csum[(size_t)blk * DD + d] = s;
}

__global__ __launch_bounds__(64) void k_csum_b() {
    int bh = blockIdx.x;
    int d = threadIdx.x;
    float run = 0.f;
    for (int ch = 0; ch < NCH; ch++) {
        size_t off = ((size_t)(bh * NCH + ch)) * DD + d;
        float t = g_csum[off];
        g_csum[off] = run;     // exclusive prefix
        run += t;
    }
}

__global__ __launch_bounds__(64) void k_csum_c(const float* __restrict__ v,
                                               float* __restrict__ out) {
    int blk = blockIdx.x;
    int bh = blk >> 7, ch = blk & (NCH - 1);
    int b = bh >> 3, h = bh & 7;
    int d = threadIdx.x;
    float acc = g_csum[(size_t)blk * DD + d];
    const float* base = v + ((size_t)(b * LL + ch * CH) * HH + h) * DD + d;
    float* obase = out + ((size_t)bh * LL + ch * CH) * DD + d;
#pragma unroll 4
    for (int i = 0; i < CH; i++) {
        acc += base[(size_t)i * HH * DD];
        obase[(size_t)i * DD] = acc;
    }
}

// ============================================================================
// Final scatter: overwrite selected rows with the attention results
// ============================================================================
__global__ __launch_bounds__(64) void k_scatter(float* __restrict__ out) {
    int row = blockIdx.x;                 // bh*NT + u
    int bh = row / NT;
    int pos = g_Mtop[row];
    int d = threadIdx.x;
    out[((size_t)bh * LL + pos) * DD + d] = g_oatt[(size_t)row * DD + d];
}

// ============================================================================
extern "C" void kernel_launch(void* const* d_in, const int* in_sizes, int n_in,
                              void* d_out, int out_size) {
    const float* q   = (const float*)d_in[0];
    const float* k   = (const float*)d_in[1];
    const float* v   = (const float*)d_in[2];
    const int*   idx = (const int*)d_in[3];
    float* out = (float*)d_out;
    (void)in_sizes; (void)n_in; (void)out_size;

    k_m      <<<BB * LL / 4, 256>>>(q, k, idx);
    k_topk   <<<BH, 256>>>();
    k_zero   <<<(BH * NT * DD + 255) / 256, 256>>>();
    k_logits <<<BH * SEG, 192>>>(q, k);
    k_softmax<<<BH * NT, 128>>>();
    k_pv     <<<BH * SEG, 192>>>(v);
    k_csum_a <<<BH * NCH, 64>>>(v);
    k_csum_b <<<BH, 64>>>();
    k_csum_c <<<BH * NCH, 64>>>(v, out);
    k_scatter<<<BH * NT, 64>>>(out);
}

// round 16
// speedup vs baseline: 1.1623x; 1.1623x over previous
#include <cuda_runtime.h>
#include <cstdint>

typedef unsigned long long ull;

#define BB 4
#define LL 4096
#define HH 8
#define DD 64
#define SK 45
#define NT 45
#define BH (BB*HH)      /* 32 */
#define SEG 16
#define KSEG (LL/SEG)   /* 256 keys per segment */
#define KT 32           /* keys per smem tile */
#define PAD 68          /* floats per padded smem row (272B: conflict-free) */
#define CH 32           /* cumsum chunk length */
#define NCH (LL/CH)     /* 128 chunks */

// ---------------- scratch (__device__ globals: no allocation allowed) -------
__device__ float g_M[BB*HH*LL];              // 512 KB
__device__ int   g_Mtop[BB*HH*NT];
__device__ float g_logits[(size_t)BB*HH*NT*LL]; // 23.6 MB (logits, then probs)
__device__ float g_oatt[BB*HH*NT*DD];        // attention rows (atomic accum)
__device__ float g_csum[BB*HH*NCH*DD];       // chunk sums / exclusive prefixes

// ---------------- packed f32x2 helpers --------------------------------------
__device__ __forceinline__ void fma2(ull& d, ull a, ull b) {
    asm("fma.rn.f32x2 %0, %1, %2, %0;" : "+l"(d) : "l"(a), "l"(b));
}
__device__ __forceinline__ void add2(ull& a, ull b) {
    asm("add.rn.f32x2 %0, %0, %1;" : "+l"(a) : "l"(b));
}
__device__ __forceinline__ ull pack2(float a, float b) {
    ull r; asm("mov.b64 %0, {%1, %2};" : "=l"(r) : "f"(a), "f"(b)); return r;
}
__device__ __forceinline__ float f2lo(ull x) { return __uint_as_float((unsigned)x); }
__device__ __forceinline__ float f2hi(ull x) { return __uint_as_float((unsigned)(x >> 32)); }

// ============================================================================
// Kernel 1 (v5, kept from R15 — measured ~60us better than v4):
// M[b,h,l] = max_j(q·k_sample_j) - sum_j(q·k_sample_j)/L
// 8-lane groups: group owns one (query, head); lane e covers 16B chunks
// e, e+8 of the 256B row -> each warp LDG.128 covers 4 fully-used 128B lines.
// Block = 4 queries x 8 heads (one b). idx staged in smem.
// ============================================================================
__global__ __launch_bounds__(256) void k_m(const float* __restrict__ q,
                                           const float* __restrict__ k,
                                           const int* __restrict__ idx) {
    __shared__ int sidx[4 * 48];
    int tid = threadIdx.x;
    int qy0 = blockIdx.x * 4;                    // 4 queries per block
    int b  = qy0 >> 12;
    int l0 = qy0 & (LL - 1);

    for (int i = tid; i < 4 * SK; i += 256) {
        int ql = i / SK, j = i - ql * SK;
        sidx[ql * 48 + j] = idx[(size_t)(l0 + ql) * SK + j];
    }
    __syncthreads();

    int wid = tid >> 5, lane = tid & 31;
    int ql = wid >> 1;                           // 0..3
    int h  = ((wid & 1) << 2) + (lane >> 3);     // head 0..7
    int e  = lane & 7;                           // octant of the 256B row
    int l  = l0 + ql;

    const float* qrow = q + ((size_t)(b * LL + l) * HH + h) * DD;
    ull qd[4];
#pragma unroll
    for (int i = 0; i < 2; i++) {
        ulonglong2 v = *(const ulonglong2*)(qrow + i * 32 + e * 4);
        qd[2*i] = v.x; qd[2*i+1] = v.y;
    }

    const float* kbase = k + (size_t)b * LL * HH * DD + h * DD;
    const int* srow = &sidx[ql * 48];

    float mx = -INFINITY, sm = 0.f;
#pragma unroll 3
    for (int j = 0; j < SK; j++) {
        int ki = srow[j];
        const float* krow = kbase + (size_t)ki * (HH * DD);
        ull a0 = 0, a1 = 0;
#pragma unroll
        for (int i = 0; i < 2; i++) {
            ulonglong2 v = *(const ulonglong2*)(krow + i * 32 + e * 4);
            fma2(a0, qd[2*i],   v.x);
            fma2(a1, qd[2*i+1], v.y);
        }
        add2(a0, a1);
        float sh = f2lo(a0) + f2hi(a0);
        sh += __shfl_xor_sync(0xffffffffu, sh, 1);
        sh += __shfl_xor_sync(0xffffffffu, sh, 2);
        sh += __shfl_xor_sync(0xffffffffu, sh, 4);
        mx = fmaxf(mx, sh);
        sm += sh;
    }
    if (e == 0) g_M[(size_t)(b * HH + h) * LL + l] = mx - sm * (1.0f / LL);
}

// ============================================================================
// Kernel 2: stable top-45 per (b,h) via iterative argmax (ties -> min index,
// matching jax.lax.top_k). Winners sorted ascending.
// ============================================================================
__global__ __launch_bounds__(256) void k_topk() {
    int bh  = blockIdx.x;
    int tid = threadIdx.x;   // 256
    __shared__ float wv[8];
    __shared__ int   wi[8];
    __shared__ int   winner;
    __shared__ int   winners[NT];

    float rv[16];
#pragma unroll
    for (int s = 0; s < 16; s++) rv[s] = g_M[(size_t)bh * LL + tid + s * 256];

    for (int it = 0; it < NT; it++) {
        float bv = -INFINITY; int bi = 1 << 30;
#pragma unroll
        for (int s = 0; s < 16; s++) {
            int i = tid + s * 256;
            float v = rv[s];
            if (v > bv || (v == bv && i < bi)) { bv = v; bi = i; }
        }
        for (int o = 16; o; o >>= 1) {
            float ov = __shfl_down_sync(0xffffffffu, bv, o);
            int   oi = __shfl_down_sync(0xffffffffu, bi, o);
            if (ov > bv || (ov == bv && oi < bi)) { bv = ov; bi = oi; }
        }
        if ((tid & 31) == 0) { wv[tid >> 5] = bv; wi[tid >> 5] = bi; }
        __syncthreads();
        if (tid == 0) {
            float fv = wv[0]; int fi = wi[0];
            for (int w = 1; w < 8; w++)
                if (wv[w] > fv || (wv[w] == fv && wi[w] < fi)) { fv = wv[w]; fi = wi[w]; }
            winner = fi;
            winners[it] = fi;
        }
        __syncthreads();
        int wn = winner;
#pragma unroll
        for (int s = 0; s < 16; s++)
            if (tid + s * 256 == wn) rv[s] = -INFINITY;
        __syncthreads();
    }
    if (tid == 0) {
        int w[NT];
        for (int i = 0; i < NT; i++) w[i] = winners[i];
        for (int i = 1; i < NT; i++) {
            int x = w[i], j = i - 1;
            while (j >= 0 && w[j] > x) { w[j + 1] = w[j]; j--; }
            w[j + 1] = x;
        }
        for (int i = 0; i < NT; i++) g_Mtop[bh * NT + i] = w[i];
    }
}

// ============================================================================
// Kernel 3a (v2, reverted to R14 — measured 71.6us; v3 direct-L2 was 135us):
// logits[bh][u][k] = 0.125 * q_u · K_k   for k <= pos_u
// grid = (BH x SEG). block 256 = 64 u-groups x 4 lanes; lane j holds q chunks
// j,j+4,j+8,j+12. K staged through padded smem tiles.
// ============================================================================
__global__ __launch_bounds__(256) void k_logits(const float* __restrict__ q,
                                                const float* __restrict__ kk) {
    int bh  = blockIdx.x >> 4;
    int seg = blockIdx.x & 15;
    int b = bh >> 3, h = bh & 7;
    __shared__ __align__(16) float ks[KT * PAD];
    __shared__ int pos_s[NT];
    int tid = threadIdx.x;

    if (tid < NT) pos_s[tid] = g_Mtop[bh * NT + tid];
    __syncthreads();

    int u = tid >> 2, j = tid & 3;
    unsigned gmask = 0xFu << ((tid & 31) & ~3);
    bool act = (u < NT);
    int pos = -1;
    ull qd[8];
    if (act) {
        pos = pos_s[u];
        const float* qrow = q + ((size_t)(b * LL + pos) * HH + h) * DD;
#pragma unroll
        for (int i = 0; i < 4; i++) {
            ulonglong2 v = *(const ulonglong2*)(qrow + (j + 4 * i) * 4);
            qd[2*i] = v.x; qd[2*i+1] = v.y;
        }
    }

    int k0 = seg * KSEG;
    for (int tile = 0; tile < KSEG / KT; tile++) {
        int kb = k0 + tile * KT;
        __syncthreads();
        for (int i = tid; i < KT * 16; i += 256) {
            int r = i >> 4, c = i & 15;
            const float4* kr =
                (const float4*)(kk + ((size_t)(b * LL + kb + r) * HH + h) * DD);
            *(float4*)&ks[r * PAD + c * 4] = kr[c];
        }
        __syncthreads();
        if (act && kb <= pos) {
            int kmax = pos - kb;                 // last valid local key
            if (kmax > KT - 1) kmax = KT - 1;
#pragma unroll 4
            for (int kl = 0; kl <= kmax; kl++) {
                const float* krow = &ks[kl * PAD];
                ull a0 = 0, a1 = 0;
#pragma unroll
                for (int i = 0; i < 4; i++) {
                    ulonglong2 v = *(const ulonglong2*)(krow + (j + 4 * i) * 4);
                    fma2(a0, qd[2*i],   v.x);
                    fma2(a1, qd[2*i+1], v.y);
                }
                add2(a0, a1);
                float sh = f2lo(a0) + f2hi(a0);
                sh += __shfl_xor_sync(gmask, sh, 1);
                sh += __shfl_xor_sync(gmask, sh, 2);
                if (j == 0)
                    g_logits[((size_t)(bh * NT + u)) * LL + kb + kl] = sh * 0.125f;
            }
        }
    }
}

// ============================================================================
// Kernel 3b: in-place softmax over k in [0, pos] for each of the 1440 rows
// ============================================================================
__global__ __launch_bounds__(128) void k_softmax() {
    int row = blockIdx.x;              // bh*NT + u
    int pos = g_Mtop[row];
    int n = pos + 1;
    float* lg = g_logits + (size_t)row * LL;
    int tid = threadIdx.x;             // 128 = 4 warps
    __shared__ float red[4];

    float mx = -INFINITY;
    for (int i = tid; i < n; i += 128) mx = fmaxf(mx, lg[i]);
    for (int o = 16; o; o >>= 1) mx = fmaxf(mx, __shfl_xor_sync(0xffffffffu, mx, o));
    if ((tid & 31) == 0) red[tid >> 5] = mx;
    __syncthreads();
    mx = fmaxf(fmaxf(red[0], red[1]), fmaxf(red[2], red[3]));

    float sm = 0.f;
    for (int i = tid; i < n; i += 128) sm += expf(lg[i] - mx);
    for (int o = 16; o; o >>= 1) sm += __shfl_xor_sync(0xffffffffu, sm, o);
    __syncthreads();
    if ((tid & 31) == 0) red[tid >> 5] = sm;
    __syncthreads();
    sm = red[0] + red[1] + red[2] + red[3];

    float inv = 1.0f / sm;
    for (int i = tid; i < n; i += 128) lg[i] = expf(lg[i] - mx) * inv;
}

// ============================================================================
// zero the attention-output accumulator
// ============================================================================
__global__ void k_zero() {
    int i = blockIdx.x * 256 + threadIdx.x;
    if (i < BH * NT * DD) g_oatt[i] = 0.f;
}

// ============================================================================
// Kernel 3c (reverted to R14): out_attn += sum_k p[u][k] * V[k][:]
// split-K over segments, V staged through smem, probs staged per tile.
// ============================================================================
__global__ __launch_bounds__(256) void k_pv(const float* __restrict__ v) {
    int bh  = blockIdx.x >> 4;
    int seg = blockIdx.x & 15;
    int b = bh >> 3, h = bh & 7;
    __shared__ __align__(16) float vs[KT * PAD];
    __shared__ float ps[NT * KT];
    __shared__ int pos_s[NT];
    int tid = threadIdx.x;

    if (tid < NT) pos_s[tid] = g_Mtop[bh * NT + tid];
    __syncthreads();

    int u = tid >> 2, dq = tid & 3;
    bool act = (u < NT);
    int pos = act ? pos_s[u] : -1;
    ull acc[8];
#pragma unroll
    for (int i = 0; i < 8; i++) acc[i] = 0;

    int k0 = seg * KSEG;
    for (int tile = 0; tile < KSEG / KT; tile++) {
        int kb = k0 + tile * KT;
        __syncthreads();
        for (int i = tid; i < KT * 16; i += 256) {
            int r = i >> 4, c = i & 15;
            const float4* vr =
                (const float4*)(v + ((size_t)(b * LL + kb + r) * HH + h) * DD);
            *(float4*)&vs[r * PAD + c * 4] = vr[c];
        }
        for (int i = tid; i < NT * KT; i += 256) {
            int uu = i >> 5, kl = i & 31;
            int kg = kb + kl;
            ps[i] = (kg <= pos_s[uu])
                      ? g_logits[((size_t)(bh * NT + uu)) * LL + kg] : 0.f;
        }
        __syncthreads();
        if (act && kb <= pos) {
#pragma unroll 1
            for (int kl = 0; kl < KT; kl++) {
                float p = ps[u * KT + kl];
                ull pp = pack2(p, p);
                const ulonglong2* vrow = (const ulonglong2*)&vs[kl * PAD + dq * 16];
                ulonglong2 v0 = vrow[0], v1 = vrow[1], v2 = vrow[2], v3 = vrow[3];
                fma2(acc[0], pp, v0.x); fma2(acc[1], pp, v0.y);
                fma2(acc[2], pp, v1.x); fma2(acc[3], pp, v1.y);
                fma2(acc[4], pp, v2.x); fma2(acc[5], pp, v2.y);
                fma2(acc[6], pp, v3.x); fma2(acc[7], pp, v3.y);
            }
        }
    }
    if (act) {
        float* dst = g_oatt + ((size_t)(bh * NT + u)) * DD + dq * 16;
#pragma unroll
        for (int i = 0; i < 8; i++) {
            atomicAdd(dst + 2 * i,     f2lo(acc[i]));
            atomicAdd(dst + 2 * i + 1, f2hi(acc[i]));
        }
    }
}

// ============================================================================
// cumsum(V) over L, chunked 3-phase scan (CH=32),
// with [B,L,H,D] -> [B,H,L,D] transpose on output
// ============================================================================
__global__ __launch_bounds__(64) void k_csum_a(const float* __restrict__ v) {
    int blk = blockIdx.x;                 // bh*NCH + ch
    int bh = blk >> 7, ch = blk & (NCH - 1);
    int b = bh >> 3, h = bh & 7;
    int d = threadIdx.x;
    float s = 0.f;
    const float* base = v + ((size_t)(b * LL + ch * CH) * HH + h) * DD + d;
#pragma unroll 4
    for (int i = 0; i < CH; i++) s += base[(size_t)i * HH * DD];
    g_csum[(size_t)blk * DD + d] = s;
}

__global__ __launch_bounds__(64) void k_csum_b() {
    int bh = blockIdx.x;
    int d = threadIdx.x;
    float run = 0.f;
    for (int ch = 0; ch < NCH; ch++) {
        size_t off = ((size_t)(bh * NCH + ch)) * DD + d;
        float t = g_csum[off];
        g_csum[off] = run;     // exclusive prefix
        run += t;
    }
}

__global__ __launch_bounds__(64) void k_csum_c(const float* __restrict__ v,
                                               float* __restrict__ out) {
    int blk = blockIdx.x;
    int bh = blk >> 7, ch = blk & (NCH - 1);
    int b = bh >> 3, h = bh & 7;
    int d = threadIdx.x;
    float acc = g_csum[(size_t)blk * DD + d];
    const float* base = v + ((size_t)(b * LL + ch * CH) * HH + h) * DD + d;
    float* obase = out + ((size_t)bh * LL + ch * CH) * DD + d;
#pragma unroll 4
    for (int i = 0; i < CH; i++) {
        acc += base[(size_t)i * HH * DD];
        obase[(size_t)i * DD] = acc;
    }
}

// ============================================================================
// Final scatter: overwrite selected rows with the attention results
// ============================================================================
__global__ __launch_bounds__(64) void k_scatter(float* __restrict__ out) {
    int row = blockIdx.x;                 // bh*NT + u
    int bh = row / NT;
    int pos = g_Mtop[row];
    int d = threadIdx.x;
    out[((size_t)bh * LL + pos) * DD + d] = g_oatt[(size_t)row * DD + d];
}

// ============================================================================
extern "C" void kernel_launch(void* const* d_in, const int* in_sizes, int n_in,
                              void* d_out, int out_size) {
    const float* q   = (const float*)d_in[0];
    const float* k   = (const float*)d_in[1];
    const float* v   = (const float*)d_in[2];
    const int*   idx = (const int*)d_in[3];
    float* out = (float*)d_out;
    (void)in_sizes; (void)n_in; (void)out_size;

    k_m      <<<BB * LL / 4, 256>>>(q, k, idx);
    k_topk   <<<BH, 256>>>();
    k_zero   <<<(BH * NT * DD + 255) / 256, 256>>>();
    k_logits <<<BH * SEG, 256>>>(q, k);
    k_softmax<<<BH * NT, 128>>>();
    k_pv     <<<BH * SEG, 256>>>(v);
    k_csum_a <<<BH * NCH, 64>>>(v);
    k_csum_b <<<BH, 64>>>();
    k_csum_c <<<BH * NCH, 64>>>(v, out);
    k_scatter<<<BH * NT, 64>>>(out);
}

// round 17
// speedup vs baseline: 1.1858x; 1.0202x over previous
#include <cuda_runtime.h>
#include <cstdint>

typedef unsigned long long ull;

#define BB 4
#define LL 4096
#define HH 8
#define DD 64
#define SK 45
#define NT 45
#define BH (BB*HH)      /* 32 */
#define SEG 16
#define KSEG (LL/SEG)   /* 256 keys per segment */
#define KT 32           /* keys per smem tile */
#define PAD 68          /* floats per padded smem row (272B: conflict-free) */
#define CH 32           /* cumsum chunk length */
#define NCH (LL/CH)     /* 128 chunks */

/* fused-kernel grid partitions */
#define GM   (BB*LL/4)                 /* 4096 k_m blocks            */
#define GA   (BH*NCH/4)                /* 1024 csum_a blocks (4 ch)  */
#define GZ   ((BH*NT*DD)/256)          /* 360 zero blocks            */
#define GLOG (BH*SEG)                  /* 512 logits blocks          */
#define GC   (BH*NCH/4)                /* 1024 csum_c blocks         */

// ---------------- scratch (__device__ globals: no allocation allowed) -------
__device__ float g_M[BB*HH*LL];              // 512 KB
__device__ int   g_Mtop[BB*HH*NT];
__device__ float g_logits[(size_t)BB*HH*NT*LL]; // 23.6 MB (logits, then probs)
__device__ float g_oatt[BB*HH*NT*DD];        // attention rows (atomic accum)
__device__ float g_csum[BB*HH*NCH*DD];       // chunk sums / exclusive prefixes

// ---------------- packed f32x2 helpers --------------------------------------
__device__ __forceinline__ void fma2(ull& d, ull a, ull b) {
    asm("fma.rn.f32x2 %0, %1, %2, %0;" : "+l"(d) : "l"(a), "l"(b));
}
__device__ __forceinline__ void add2(ull& a, ull b) {
    asm("add.rn.f32x2 %0, %0, %1;" : "+l"(a) : "l"(b));
}
__device__ __forceinline__ ull pack2(float a, float b) {
    ull r; asm("mov.b64 %0, {%1, %2};" : "=l"(r) : "f"(a), "f"(b)); return r;
}
__device__ __forceinline__ float f2lo(ull x) { return __uint_as_float((unsigned)x); }
__device__ __forceinline__ float f2hi(ull x) { return __uint_as_float((unsigned)(x >> 32)); }

// transposed u-assignment: warp gets ranks spread across 0..63 (load balance)
__device__ __forceinline__ int umap(int slot) {
    return ((slot & 7) << 3) + (slot >> 3);
}

// ============================================================================
// K1 = k_m  ∪  csum_a  ∪  zero   (mutually independent work, one launch)
// ============================================================================
__global__ __launch_bounds__(256) void k_fuse1(const float* __restrict__ q,
                                               const float* __restrict__ k,
                                               const float* __restrict__ v,
                                               const int* __restrict__ idx) {
    int tid = threadIdx.x;
    unsigned bx = blockIdx.x;

    if (bx < GM) {
        // ---- k_m v5: 8-lane groups, block = 4 queries x 8 heads ----
        __shared__ int sidx[4 * 48];
        int qy0 = bx * 4;
        int b  = qy0 >> 12;
        int l0 = qy0 & (LL - 1);

        for (int i = tid; i < 4 * SK; i += 256) {
            int ql = i / SK, j = i - ql * SK;
            sidx[ql * 48 + j] = idx[(size_t)(l0 + ql) * SK + j];
        }
        __syncthreads();

        int wid = tid >> 5, lane = tid & 31;
        int ql = wid >> 1;
        int h  = ((wid & 1) << 2) + (lane >> 3);
        int e  = lane & 7;
        int l  = l0 + ql;

        const float* qrow = q + ((size_t)(b * LL + l) * HH + h) * DD;
        ull qd[4];
#pragma unroll
        for (int i = 0; i < 2; i++) {
            ulonglong2 vv = *(const ulonglong2*)(qrow + i * 32 + e * 4);
            qd[2*i] = vv.x; qd[2*i+1] = vv.y;
        }

        const float* kbase = k + (size_t)b * LL * HH * DD + h * DD;
        const int* srow = &sidx[ql * 48];

        float mx = -INFINITY, sm = 0.f;
#pragma unroll 3
        for (int j = 0; j < SK; j++) {
            int ki = srow[j];
            const float* krow = kbase + (size_t)ki * (HH * DD);
            ull a0 = 0, a1 = 0;
#pragma unroll
            for (int i = 0; i < 2; i++) {
                ulonglong2 vv = *(const ulonglong2*)(krow + i * 32 + e * 4);
                fma2(a0, qd[2*i],   vv.x);
                fma2(a1, qd[2*i+1], vv.y);
            }
            add2(a0, a1);
            float sh = f2lo(a0) + f2hi(a0);
            sh += __shfl_xor_sync(0xffffffffu, sh, 1);
            sh += __shfl_xor_sync(0xffffffffu, sh, 2);
            sh += __shfl_xor_sync(0xffffffffu, sh, 4);
            mx = fmaxf(mx, sh);
            sm += sh;
        }
        if (e == 0) g_M[(size_t)(b * HH + h) * LL + l] = mx - sm * (1.0f / LL);

    } else if (bx < GM + GA) {
        // ---- csum_a: per-chunk sums (4 chunk-tasks per block) ----
        int task = (bx - GM) * 4 + (tid >> 6);
        int bh = task >> 7, ch = task & (NCH - 1);
        int b = bh >> 3, h = bh & 7;
        int d = tid & 63;
        float s = 0.f;
        const float* base = v + ((size_t)(b * LL + ch * CH) * HH + h) * DD + d;
#pragma unroll 4
        for (int i = 0; i < CH; i++) s += base[(size_t)i * HH * DD];
        g_csum[(size_t)task * DD + d] = s;

    } else {
        // ---- zero the attention accumulator ----
        int i = (bx - GM - GA) * 256 + tid;
        g_oatt[i] = 0.f;
    }
}

// ============================================================================
// K2 = topk  ∪  csum_b
// ============================================================================
__global__ __launch_bounds__(256) void k_fuse2() {
    int tid = threadIdx.x;
    if (blockIdx.x >= BH) {
        // ---- csum_b: serial exclusive prefix over chunk sums ----
        int bh = blockIdx.x - BH;
        if (tid < 64) {
            int d = tid;
            float run = 0.f;
            for (int ch = 0; ch < NCH; ch++) {
                size_t off = ((size_t)(bh * NCH + ch)) * DD + d;
                float t = g_csum[off];
                g_csum[off] = run;
                run += t;
            }
        }
        return;
    }
    // ---- stable top-45 (ties -> min index, matches jax.lax.top_k) ----
    int bh = blockIdx.x;
    __shared__ float wv[8];
    __shared__ int   wi[8];
    __shared__ int   winner;
    __shared__ int   winners[NT];

    float rv[16];
#pragma unroll
    for (int s = 0; s < 16; s++) rv[s] = g_M[(size_t)bh * LL + tid + s * 256];

    for (int it = 0; it < NT; it++) {
        float bv = -INFINITY; int bi = 1 << 30;
#pragma unroll
        for (int s = 0; s < 16; s++) {
            int i = tid + s * 256;
            float v = rv[s];
            if (v > bv || (v == bv && i < bi)) { bv = v; bi = i; }
        }
        for (int o = 16; o; o >>= 1) {
            float ov = __shfl_down_sync(0xffffffffu, bv, o);
            int   oi = __shfl_down_sync(0xffffffffu, bi, o);
            if (ov > bv || (ov == bv && oi < bi)) { bv = ov; bi = oi; }
        }
        if ((tid & 31) == 0) { wv[tid >> 5] = bv; wi[tid >> 5] = bi; }
        __syncthreads();
        if (tid == 0) {
            float fv = wv[0]; int fi = wi[0];
            for (int w = 1; w < 8; w++)
                if (wv[w] > fv || (wv[w] == fv && wi[w] < fi)) { fv = wv[w]; fi = wi[w]; }
            winner = fi;
            winners[it] = fi;
        }
        __syncthreads();
        int wn = winner;
#pragma unroll
        for (int s = 0; s < 16; s++)
            if (tid + s * 256 == wn) rv[s] = -INFINITY;
        __syncthreads();
    }
    if (tid == 0) {
        int w[NT];
        for (int i = 0; i < NT; i++) w[i] = winners[i];
        for (int i = 1; i < NT; i++) {
            int x = w[i], j = i - 1;
            while (j >= 0 && w[j] > x) { w[j + 1] = w[j]; j--; }
            w[j + 1] = x;
        }
        for (int i = 0; i < NT; i++) g_Mtop[bh * NT + i] = w[i];
    }
}

// ============================================================================
// K3 = logits  ∪  csum_c
// logits v4: transposed u-assignment (warp balance) + reg-staged tile
// prefetch (LDG of tile t+1 overlaps compute of tile t).
// ============================================================================
__global__ __launch_bounds__(256) void k_fuse3(const float* __restrict__ q,
                                               const float* __restrict__ kk,
                                               const float* __restrict__ v,
                                               float* __restrict__ out) {
    int tid = threadIdx.x;
    unsigned bx = blockIdx.x;

    if (bx >= GLOG) {
        // ---- csum_c: emit inclusive scan with transpose (4 tasks/block) ----
        int task = (bx - GLOG) * 4 + (tid >> 6);
        int bh = task >> 7, ch = task & (NCH - 1);
        int b = bh >> 3, h = bh & 7;
        int d = tid & 63;
        float acc = g_csum[(size_t)task * DD + d];
        const float* base = v + ((size_t)(b * LL + ch * CH) * HH + h) * DD + d;
        float* obase = out + ((size_t)bh * LL + ch * CH) * DD + d;
#pragma unroll 4
        for (int i = 0; i < CH; i++) {
            acc += base[(size_t)i * HH * DD];
            obase[(size_t)i * DD] = acc;
        }
        return;
    }

    // ---- logits ----
    int bh  = bx >> 4;
    int seg = bx & 15;
    int b = bh >> 3, h = bh & 7;
    __shared__ __align__(16) float ks[KT * PAD];
    __shared__ int pos_s[NT];

    if (tid < NT) pos_s[tid] = g_Mtop[bh * NT + tid];
    __syncthreads();

    int slot = tid >> 2, j = tid & 3;
    int u = umap(slot);
    unsigned gmask = 0xFu << ((tid & 31) & ~3);
    bool act = (u < NT);
    int pos = -1;
    ull qd[8];
    if (act) {
        pos = pos_s[u];
        const float* qrow = q + ((size_t)(b * LL + pos) * HH + h) * DD;
#pragma unroll
        for (int i = 0; i < 4; i++) {
            ulonglong2 vv = *(const ulonglong2*)(qrow + (j + 4 * i) * 4);
            qd[2*i] = vv.x; qd[2*i+1] = vv.y;
        }
    }

    // loader slots: this thread stages rows r0,r1 column c of each tile
    int r0 = tid >> 4, c0 = tid & 15;
    int r1 = r0 + 16;
    int k0 = seg * KSEG;

    // prefetch tile 0 into registers
    float4 f0 = *(const float4*)(kk + ((size_t)(b * LL + k0 + r0) * HH + h) * DD + c0 * 4);
    float4 f1 = *(const float4*)(kk + ((size_t)(b * LL + k0 + r1) * HH + h) * DD + c0 * 4);

    for (int tile = 0; tile < KSEG / KT; tile++) {
        int kb = k0 + tile * KT;
        *(float4*)&ks[r0 * PAD + c0 * 4] = f0;
        *(float4*)&ks[r1 * PAD + c0 * 4] = f1;
        __syncthreads();
        if (tile + 1 < KSEG / KT) {
            int kn = kb + KT;
            f0 = *(const float4*)(kk + ((size_t)(b * LL + kn + r0) * HH + h) * DD + c0 * 4);
            f1 = *(const float4*)(kk + ((size_t)(b * LL + kn + r1) * HH + h) * DD + c0 * 4);
        }
        if (act && kb <= pos) {
            int kmax = pos - kb;
            if (kmax > KT - 1) kmax = KT - 1;
#pragma unroll 4
            for (int kl = 0; kl <= kmax; kl++) {
                const float* krow = &ks[kl * PAD];
                ull a0 = 0, a1 = 0;
#pragma unroll
                for (int i = 0; i < 4; i++) {
                    ulonglong2 vv = *(const ulonglong2*)(krow + (j + 4 * i) * 4);
                    fma2(a0, qd[2*i],   vv.x);
                    fma2(a1, qd[2*i+1], vv.y);
                }
                add2(a0, a1);
                float sh = f2lo(a0) + f2hi(a0);
                sh += __shfl_xor_sync(gmask, sh, 1);
                sh += __shfl_xor_sync(gmask, sh, 2);
                if (j == 0)
                    g_logits[((size_t)(bh * NT + u)) * LL + kb + kl] = sh * 0.125f;
            }
        }
        __syncthreads();
    }
}

// ============================================================================
// K4: in-place softmax over k in [0, pos] for each of the 1440 rows
// ============================================================================
__global__ __launch_bounds__(128) void k_softmax() {
    int row = blockIdx.x;              // bh*NT + u
    int pos = g_Mtop[row];
    int n = pos + 1;
    float* lg = g_logits + (size_t)row * LL;
    int tid = threadIdx.x;             // 128 = 4 warps
    __shared__ float red[4];

    float mx = -INFINITY;
    for (int i = tid; i < n; i += 128) mx = fmaxf(mx, lg[i]);
    for (int o = 16; o; o >>= 1) mx = fmaxf(mx, __shfl_xor_sync(0xffffffffu, mx, o));
    if ((tid & 31) == 0) red[tid >> 5] = mx;
    __syncthreads();
    mx = fmaxf(fmaxf(red[0], red[1]), fmaxf(red[2], red[3]));

    float sm = 0.f;
    for (int i = tid; i < n; i += 128) sm += expf(lg[i] - mx);
    for (int o = 16; o; o >>= 1) sm += __shfl_xor_sync(0xffffffffu, sm, o);
    __syncthreads();
    if ((tid & 31) == 0) red[tid >> 5] = sm;
    __syncthreads();
    sm = red[0] + red[1] + red[2] + red[3];

    float inv = 1.0f / sm;
    for (int i = tid; i < n; i += 128) lg[i] = expf(lg[i] - mx) * inv;
}

// ============================================================================
// K5: PV — split-K over segments, V staged through smem, probs staged per
// tile; transposed u-assignment for warp balance.
// ============================================================================
__global__ __launch_bounds__(256) void k_pv(const float* __restrict__ v) {
    int bh  = blockIdx.x >> 4;
    int seg = blockIdx.x & 15;
    int b = bh >> 3, h = bh & 7;
    __shared__ __align__(16) float vs[KT * PAD];
    __shared__ float ps[NT * KT];
    __shared__ int pos_s[NT];
    int tid = threadIdx.x;

    if (tid < NT) pos_s[tid] = g_Mtop[bh * NT + tid];
    __syncthreads();

    int slot = tid >> 2, dq = tid & 3;
    int u = umap(slot);
    bool act = (u < NT);
    int pos = act ? pos_s[u] : -1;
    ull acc[8];
#pragma unroll
    for (int i = 0; i < 8; i++) acc[i] = 0;

    int k0 = seg * KSEG;
    for (int tile = 0; tile < KSEG / KT; tile++) {
        int kb = k0 + tile * KT;
        __syncthreads();
        for (int i = tid; i < KT * 16; i += 256) {
            int r = i >> 4, c = i & 15;
            const float4* vr =
                (const float4*)(v + ((size_t)(b * LL + kb + r) * HH + h) * DD);
            *(float4*)&vs[r * PAD + c * 4] = vr[c];
        }
        for (int i = tid; i < NT * KT; i += 256) {
            int uu = i >> 5, kl = i & 31;
            int kg = kb + kl;
            ps[i] = (kg <= pos_s[uu])
                      ? g_logits[((size_t)(bh * NT + uu)) * LL + kg] : 0.f;
        }
        __syncthreads();
        if (act && kb <= pos) {
#pragma unroll 1
            for (int kl = 0; kl < KT; kl++) {
                float p = ps[u * KT + kl];
                ull pp = pack2(p, p);
                const ulonglong2* vrow = (const ulonglong2*)&vs[kl * PAD + dq * 16];
                ulonglong2 v0 = vrow[0], v1 = vrow[1], v2 = vrow[2], v3 = vrow[3];
                fma2(acc[0], pp, v0.x); fma2(acc[1], pp, v0.y);
                fma2(acc[2], pp, v1.x); fma2(acc[3], pp, v1.y);
                fma2(acc[4], pp, v2.x); fma2(acc[5], pp, v2.y);
                fma2(acc[6], pp, v3.x); fma2(acc[7], pp, v3.y);
            }
        }
    }
    if (act) {
        float* dst = g_oatt + ((size_t)(bh * NT + u)) * DD + dq * 16;
#pragma unroll
        for (int i = 0; i < 8; i++) {
            atomicAdd(dst + 2 * i,     f2lo(acc[i]));
            atomicAdd(dst + 2 * i + 1, f2hi(acc[i]));
        }
    }
}

// ============================================================================
// K6: final scatter — overwrite selected rows with the attention results
// ============================================================================
__global__ __launch_bounds__(64) void k_scatter(float* __restrict__ out) {
    int row = blockIdx.x;                 // bh*NT + u
    int bh = row / NT;
    int pos = g_Mtop[row];
    int d = threadIdx.x;
    out[((size_t)bh * LL + pos) * DD + d] = g_oatt[(size_t)row * DD + d];
}

// ============================================================================
extern "C" void kernel_launch(void* const* d_in, const int* in_sizes, int n_in,
                              void* d_out, int out_size) {
    const float* q   = (const float*)d_in[0];
    const float* k   = (const float*)d_in[1];
    const float* v   = (const float*)d_in[2];
    const int*   idx = (const int*)d_in[3];
    float* out = (float*)d_out;
    (void)in_sizes; (void)n_in; (void)out_size;

    k_fuse1  <<<GM + GA + GZ, 256>>>(q, k, v, idx);
    k_fuse2  <<<2 * BH, 256>>>();
    k_fuse3  <<<GLOG + GC, 256>>>(q, k, v, out);
    k_softmax<<<BH * NT, 128>>>();
    k_pv     <<<BH * SEG, 256>>>(v);
    k_scatter<<<BH * NT, 64>>>(out);
}